// round 2
// baseline (speedup 1.0000x reference)
#include <cuda_runtime.h>

#define NIMG 96
#define HH 512
#define WW 512
#define HS 256   // H/2
#define WS 256   // W/2

// Scratch (device globals: no runtime allocation allowed)
__device__ float g_cA[NIMG * HS * WS];              // 25.2 MB
__device__ float g_s1[NIMG * 16 * 128 * 128];       // 100.7 MB
__device__ float g_s2[NIMG * 8 * 64 * 64];          // 12.6 MB

// ---------------------------------------------------------------------------
// Kernel 1: Haar DWT. cA -> g_cA, cH/cV -> d_out "high" region directly.
// high layout per img: [cH (256*256), cV (256*256)], img = b*3+c ordering
// matches flat reshape.
// grid: (256 rows, 96 imgs), block: 128 threads, each thread -> 2 out cols.
// ---------------------------------------------------------------------------
__global__ void dwt_kernel(const float* __restrict__ x, float* __restrict__ high) {
    int i   = blockIdx.x;    // output row 0..255
    int img = blockIdx.y;    // 0..95
    int t   = threadIdx.x;   // 0..127

    const float4* r0 = (const float4*)(x + ((size_t)img * HH + 2 * i) * WW);
    const float4* r1 = r0 + (WW / 4);
    float4 t0 = r0[t];
    float4 t1 = r1[t];

    float a0 = t0.x, b0 = t0.y, c0 = t1.x, d0 = t1.y;
    float a1 = t0.z, b1 = t0.w, c1 = t1.z, d1 = t1.w;

    float2 vA = make_float2(0.5f * (a0 + b0 + c0 + d0), 0.5f * (a1 + b1 + c1 + d1));
    float2 vH = make_float2(0.5f * (a0 + b0 - c0 - d0), 0.5f * (a1 + b1 - c1 - d1));
    float2 vV = make_float2(0.5f * (a0 - b0 + c0 - d0), 0.5f * (a1 - b1 + c1 - d1));

    size_t oA = (size_t)img * HS * WS + (size_t)i * WS + 2 * t;
    *(float2*)(g_cA + oA) = vA;

    size_t oH = (size_t)img * (2 * HS * WS) + (size_t)i * WS + 2 * t;
    *(float2*)(high + oH) = vH;
    *(float2*)(high + oH + HS * WS) = vV;
}

// ---------------------------------------------------------------------------
// Kernel 2: conv3x3 SAME (1->16) + relu + maxpool2 fused.
// in: g_cA [96,1,256,256], out: g_s1 [96,16,128,128]
// block 16x16 threads; each thread = 1 pooled output pixel, all 16 oc.
// ---------------------------------------------------------------------------
__global__ void conv1_kernel(const float* __restrict__ w1, const float* __restrict__ b1) {
    __shared__ float tile[34][36];   // padded cols to dodge bank conflicts
    __shared__ float ws[16 * 9];
    __shared__ float bs[16];

    int tx = threadIdx.x, ty = threadIdx.y;
    int tid = ty * 16 + tx;
    int px0 = blockIdx.x * 16, py0 = blockIdx.y * 16;  // pooled-space origin
    int img = blockIdx.z;

    if (tid < 144) ws[tid] = w1[tid];
    if (tid < 16)  bs[tid] = b1[tid];

    const float* in = g_cA + (size_t)img * HS * WS;
    int r0 = 2 * py0 - 1, c0 = 2 * px0 - 1;
    for (int k = tid; k < 34 * 34; k += 256) {
        int r = k / 34, c = k % 34;
        int ir = r0 + r, ic = c0 + c;
        float v = 0.f;
        if (ir >= 0 && ir < HS && ic >= 0 && ic < WS) v = in[(size_t)ir * WS + ic];
        tile[r][c] = v;
    }
    __syncthreads();

    // 4x4 input patch for this thread's 2x2 conv quad
    float p[4][4];
#pragma unroll
    for (int r = 0; r < 4; r++)
#pragma unroll
        for (int c = 0; c < 4; c++)
            p[r][c] = tile[2 * ty + r][2 * tx + c];

    float* out = g_s1 + (size_t)img * 16 * 128 * 128;
    int oy = py0 + ty, ox = px0 + tx;

#pragma unroll
    for (int oc = 0; oc < 16; oc++) {
        float wv[9];
#pragma unroll
        for (int k = 0; k < 9; k++) wv[k] = ws[oc * 9 + k];
        float bias = bs[oc];
        float m = 0.f;   // max(relu(s)) == max(0, s0..s3)
#pragma unroll
        for (int dy = 0; dy < 2; dy++)
#pragma unroll
            for (int dx = 0; dx < 2; dx++) {
                float s = bias;
#pragma unroll
                for (int ky = 0; ky < 3; ky++)
#pragma unroll
                    for (int kx = 0; kx < 3; kx++)
                        s = fmaf(wv[ky * 3 + kx], p[dy + ky][dx + kx], s);
                m = fmaxf(m, s);
            }
        out[((size_t)oc * 128 + oy) * 128 + ox] = m;
    }
}

// ---------------------------------------------------------------------------
// Kernel 3: conv3x3 SAME (16->8) + relu + maxpool2 fused.
// in: g_s1 [96,16,128,128], out: g_s2 [96,8,64,64]
// block 16x16; loop over 16 input channels, smem tile per channel.
// ---------------------------------------------------------------------------
__global__ void conv2_kernel(const float* __restrict__ w2, const float* __restrict__ b2) {
    __shared__ float tile[34][36];
    __shared__ float ws[8 * 16 * 9];
    __shared__ float bs[8];

    int tx = threadIdx.x, ty = threadIdx.y;
    int tid = ty * 16 + tx;
    int px0 = blockIdx.x * 16, py0 = blockIdx.y * 16;  // pooled-space (64) origin
    int img = blockIdx.z;

    for (int k = tid; k < 1152; k += 256) ws[k] = w2[k];
    if (tid < 8) bs[tid] = b2[tid];

    float acc[8][4];
#pragma unroll
    for (int oc = 0; oc < 8; oc++)
#pragma unroll
        for (int q = 0; q < 4; q++) acc[oc][q] = 0.f;

    const float* inb = g_s1 + (size_t)img * 16 * 128 * 128;
    int r0 = 2 * py0 - 1, c0 = 2 * px0 - 1;

    for (int ic = 0; ic < 16; ic++) {
        __syncthreads();  // protects tile reuse (and covers weight load at ic=0)
        const float* in = inb + (size_t)ic * 128 * 128;
        for (int k = tid; k < 34 * 34; k += 256) {
            int r = k / 34, c = k % 34;
            int ir = r0 + r, icc = c0 + c;
            float v = 0.f;
            if (ir >= 0 && ir < 128 && icc >= 0 && icc < 128) v = in[ir * 128 + icc];
            tile[r][c] = v;
        }
        __syncthreads();

        float p[4][4];
#pragma unroll
        for (int r = 0; r < 4; r++)
#pragma unroll
            for (int c = 0; c < 4; c++)
                p[r][c] = tile[2 * ty + r][2 * tx + c];

#pragma unroll
        for (int oc = 0; oc < 8; oc++) {
            const float* wp = &ws[(oc * 16 + ic) * 9];
            float wv[9];
#pragma unroll
            for (int k = 0; k < 9; k++) wv[k] = wp[k];
#pragma unroll
            for (int dy = 0; dy < 2; dy++)
#pragma unroll
                for (int dx = 0; dx < 2; dx++) {
                    float s = acc[oc][dy * 2 + dx];
#pragma unroll
                    for (int ky = 0; ky < 3; ky++)
#pragma unroll
                        for (int kx = 0; kx < 3; kx++)
                            s = fmaf(wv[ky * 3 + kx], p[dy + ky][dx + kx], s);
                    acc[oc][dy * 2 + dx] = s;
                }
        }
    }

    float* out = g_s2 + (size_t)img * 8 * 64 * 64;
    int oy = py0 + ty, ox = px0 + tx;
#pragma unroll
    for (int oc = 0; oc < 8; oc++) {
        float m = 0.f;
#pragma unroll
        for (int q = 0; q < 4; q++) m = fmaxf(m, acc[oc][q] + bs[oc]);
        out[((size_t)oc * 64 + oy) * 64 + ox] = m;
    }
}

// ---------------------------------------------------------------------------
// Kernel 4: conv1x1 (8->4), write "low" region of d_out.
// low layout: [96, 4, 64, 64] flattened (== reshape(32,1,-1))
// ---------------------------------------------------------------------------
__global__ void conv3_kernel(const float* __restrict__ w3, const float* __restrict__ b3,
                             float* __restrict__ low) {
    __shared__ float ws[32];
    __shared__ float bs[4];
    int tid = threadIdx.x;
    if (tid < 32) ws[tid] = w3[tid];
    if (tid < 4)  bs[tid] = b3[tid];
    __syncthreads();

    int idx = blockIdx.x * blockDim.x + tid;  // 0 .. 96*4096-1
    int img = idx >> 12;
    int p   = idx & 4095;

    const float* in = g_s2 + (size_t)img * 8 * 4096 + p;
    float v[8];
#pragma unroll
    for (int ic = 0; ic < 8; ic++) v[ic] = in[(size_t)ic * 4096];

#pragma unroll
    for (int oc = 0; oc < 4; oc++) {
        float s = bs[oc];
#pragma unroll
        for (int ic = 0; ic < 8; ic++) s = fmaf(ws[oc * 8 + ic], v[ic], s);
        low[((size_t)img * 4 + oc) * 4096 + p] = s;
    }
}

// ---------------------------------------------------------------------------
extern "C" void kernel_launch(void* const* d_in, const int* in_sizes, int n_in,
                              void* d_out, int out_size) {
    const float* x  = (const float*)d_in[0];
    const float* w1 = (const float*)d_in[1];
    const float* b1 = (const float*)d_in[2];
    const float* w2 = (const float*)d_in[3];
    const float* b2 = (const float*)d_in[4];
    const float* w3 = (const float*)d_in[5];
    const float* b3 = (const float*)d_in[6];

    float* out  = (float*)d_out;
    float* low  = out;                    // 96*4*64*64 = 1,572,864 floats
    float* high = out + 1572864;          // 96*2*256*256 = 12,582,912 floats

    dwt_kernel<<<dim3(256, 96), 128>>>(x, high);
    conv1_kernel<<<dim3(8, 8, NIMG), dim3(16, 16)>>>(w1, b1);
    conv2_kernel<<<dim3(4, 4, NIMG), dim3(16, 16)>>>(w2, b2);
    conv3_kernel<<<(NIMG * 4096) / 256, 256>>>(w3, b3, low);
}

// round 5
// speedup vs baseline: 1.4593x; 1.4593x over previous
#include <cuda_runtime.h>

#define NIMG 96
#define HH 512
#define WW 512
#define HS 256   // cA resolution
#define WS 256

typedef unsigned long long ull;

__device__ __forceinline__ ull pk2(float lo, float hi) {
    ull r; asm("mov.b64 %0, {%1, %2};" : "=l"(r) : "f"(lo), "f"(hi)); return r;
}
__device__ __forceinline__ void upk2(ull v, float& lo, float& hi) {
    asm("mov.b64 {%0, %1}, %2;" : "=f"(lo), "=f"(hi) : "l"(v));
}
__device__ __forceinline__ void fma2(ull& d, ull a, ull b) {
    asm("fma.rn.f32x2 %0, %1, %2, %0;" : "+l"(d) : "l"(a), "l"(b));
}

// Scratch: only cA survives between kernels now
__device__ float g_cA[NIMG * HS * WS];   // 25.2 MB

// ---------------------------------------------------------------------------
// Kernel 1: Haar DWT. cA -> g_cA, cH/cV -> d_out "high" region directly.
// ---------------------------------------------------------------------------
__global__ void dwt_kernel(const float* __restrict__ x, float* __restrict__ high) {
    int i   = blockIdx.x;    // output row 0..255
    int img = blockIdx.y;    // 0..95
    int t   = threadIdx.x;   // 0..127

    const float4* r0 = (const float4*)(x + ((size_t)img * HH + 2 * i) * WW);
    const float4* r1 = r0 + (WW / 4);
    float4 t0 = r0[t];
    float4 t1 = r1[t];

    float a0 = t0.x, b0 = t0.y, c0 = t1.x, d0 = t1.y;
    float a1 = t0.z, b1 = t0.w, c1 = t1.z, d1 = t1.w;

    float2 vA = make_float2(0.5f * (a0 + b0 + c0 + d0), 0.5f * (a1 + b1 + c1 + d1));
    float2 vH = make_float2(0.5f * (a0 + b0 - c0 - d0), 0.5f * (a1 + b1 - c1 - d1));
    float2 vV = make_float2(0.5f * (a0 - b0 + c0 - d0), 0.5f * (a1 - b1 + c1 - d1));

    size_t oA = (size_t)img * HS * WS + (size_t)i * WS + 2 * t;
    *(float2*)(g_cA + oA) = vA;

    size_t oH = (size_t)img * (2 * HS * WS) + (size_t)i * WS + 2 * t;
    *(float2*)(high + oH) = vH;
    *(float2*)(high + oH + HS * WS) = vV;
}

// ---------------------------------------------------------------------------
// Kernel 2: FUSED conv1(1->16,3x3)+relu+pool + conv2(16->8,3x3)+relu+pool
//           + conv3(8->4,1x1). cA in, "low" out. No intermediates in HBM.
//
// Block = 16x16 threads = one 16x16 tile of pooled-64 output, grid (4,4,96).
// Per block: load 70x70 cA tile once; for each of 16 conv1 channels, compute
// the 34x34 s1 tile (conv1+relu+pool, f32x2 dx-paired) into smem, then
// accumulate conv2 (f32x2 oc-paired). Epilogue applies bias/relu/pool and
// the 1x1 conv3, writing 4 output channels.
// ---------------------------------------------------------------------------
__global__ void __launch_bounds__(256) fused_kernel(
    const float* __restrict__ w1, const float* __restrict__ b1,
    const float* __restrict__ w2, const float* __restrict__ b2,
    const float* __restrict__ w3, const float* __restrict__ b3,
    float* __restrict__ low)
{
    __shared__ __align__(16) float cAt[70][72];   // 20.2 KB
    __shared__ __align__(16) float s1t[34][36];   //  4.9 KB
    __shared__ ull   w2p[16 * 9 * 4];             //  4.6 KB  (ic,k,ocpair)
    __shared__ float w1s[16 * 9];
    __shared__ float b1s[16];
    __shared__ float b2s[8];
    __shared__ float w3s[32];
    __shared__ float b3s[4];

    const int tx = threadIdx.x, ty = threadIdx.y;
    const int tid = ty * 16 + tx;
    const int px0 = blockIdx.x * 16, py0 = blockIdx.y * 16;  // pooled-64 origin
    const int img = blockIdx.z;

    // ---- weights to smem ----
    if (tid < 144) w1s[tid] = w1[tid];
    if (tid < 16)  b1s[tid] = b1[tid];
    if (tid < 8)   b2s[tid] = b2[tid];
    if (tid < 32)  w3s[tid] = w3[tid];
    if (tid < 4)   b3s[tid] = b3[tid];
    for (int idx = tid; idx < 16 * 9 * 4; idx += 256) {
        int ocp = idx & 3;
        int k   = (idx >> 2) % 9;
        int ic  = idx / 36;
        int oc0 = 2 * ocp;
        float lo = w2[(oc0 * 16 + ic) * 9 + k];
        float hi = w2[((oc0 + 1) * 16 + ic) * 9 + k];
        w2p[idx] = pk2(lo, hi);
    }

    // ---- cA tile: 70x70 at origin (4*py0-3, 4*px0-3), zero-padded ----
    {
        const float* in = g_cA + (size_t)img * HS * WS;
        const int gr0 = 4 * py0 - 3, gc0 = 4 * px0 - 3;
        for (int k = tid; k < 70 * 70; k += 256) {
            int r = k / 70, c = k % 70;
            int ir = gr0 + r, ic = gc0 + c;
            float v = 0.f;
            if (ir >= 0 && ir < HS && ic >= 0 && ic < WS) v = in[(size_t)ir * WS + ic];
            cAt[r][c] = v;
        }
    }

    // conv2 accumulators: [quad(dy*2+dx)][ocpair], each holds oc (2p, 2p+1)
    ull acc[4][4];
#pragma unroll
    for (int q = 0; q < 4; q++)
#pragma unroll
        for (int p = 0; p < 4; p++) acc[q][p] = 0ull;

    const int r0s = 2 * py0 - 1, c0s = 2 * px0 - 1;  // s1-tile global origin

    for (int ic = 0; ic < 16; ic++) {
        __syncthreads();   // s1t free (covers initial smem fill too)

        // ---- conv1 stage: compute s1 tile for channel ic ----
        {
            float wv[9];
#pragma unroll
            for (int k = 0; k < 9; k++) wv[k] = w1s[ic * 9 + k];
            ull wq[9];
#pragma unroll
            for (int k = 0; k < 9; k++) wq[k] = pk2(wv[k], wv[k]);
            const float bias = b1s[ic];
            const ull biasq = pk2(bias, bias);

            for (int k = tid; k < 34 * 34; k += 256) {
                int r = k / 34, c = k % 34;
                // inputs: cAt[2r .. 2r+3][2c .. 2c+3]
                float p[4][4];
#pragma unroll
                for (int i = 0; i < 4; i++) {
                    float2 v0 = *(const float2*)&cAt[2 * r + i][2 * c];
                    float2 v1 = *(const float2*)&cAt[2 * r + i][2 * c + 2];
                    p[i][0] = v0.x; p[i][1] = v0.y; p[i][2] = v1.x; p[i][3] = v1.y;
                }
                ull pp[4][3];
#pragma unroll
                for (int i = 0; i < 4; i++)
#pragma unroll
                    for (int j = 0; j < 3; j++) pp[i][j] = pk2(p[i][j], p[i][j + 1]);

                ull a0 = biasq, a1 = biasq;   // (dy=0, dy=1) x (dx=0, dx=1 packed)
#pragma unroll
                for (int ky = 0; ky < 3; ky++)
#pragma unroll
                    for (int kx = 0; kx < 3; kx++) {
                        ull w = wq[ky * 3 + kx];
                        fma2(a0, w, pp[ky][kx]);
                        fma2(a1, w, pp[ky + 1][kx]);
                    }
                float s00, s01, s10, s11;
                upk2(a0, s00, s01);
                upk2(a1, s10, s11);
                float m = fmaxf(fmaxf(s00, s01), fmaxf(s10, s11));
                m = fmaxf(m, 0.f);
                // zero outside the valid 128x128 s1 grid (conv2 SAME padding)
                int rs = r0s + r, cs = c0s + c;
                if (rs < 0 || rs >= 128 || cs < 0 || cs >= 128) m = 0.f;
                s1t[r][c] = m;
            }
        }
        __syncthreads();

        // ---- conv2 stage: accumulate this input channel ----
        {
            float p[4][4];
#pragma unroll
            for (int i = 0; i < 4; i++) {
                float2 v0 = *(const float2*)&s1t[2 * ty + i][2 * tx];
                float2 v1 = *(const float2*)&s1t[2 * ty + i][2 * tx + 2];
                p[i][0] = v0.x; p[i][1] = v0.y; p[i][2] = v1.x; p[i][3] = v1.y;
            }
            ull pb[4][4];
#pragma unroll
            for (int i = 0; i < 4; i++)
#pragma unroll
                for (int j = 0; j < 4; j++) pb[i][j] = pk2(p[i][j], p[i][j]);

            const ull* wrow = &w2p[ic * 36];
#pragma unroll
            for (int ky = 0; ky < 3; ky++)
#pragma unroll
                for (int kx = 0; kx < 3; kx++) {
                    ull w0 = wrow[(ky * 3 + kx) * 4 + 0];
                    ull w1_ = wrow[(ky * 3 + kx) * 4 + 1];
                    ull w2_ = wrow[(ky * 3 + kx) * 4 + 2];
                    ull w3_ = wrow[(ky * 3 + kx) * 4 + 3];
#pragma unroll
                    for (int dy = 0; dy < 2; dy++)
#pragma unroll
                        for (int dx = 0; dx < 2; dx++) {
                            ull pv = pb[dy + ky][dx + kx];
                            int q = dy * 2 + dx;
                            fma2(acc[q][0], w0, pv);
                            fma2(acc[q][1], w1_, pv);
                            fma2(acc[q][2], w2_, pv);
                            fma2(acc[q][3], w3_, pv);
                        }
                }
        }
    }

    // ---- epilogue: bias + pool-max + relu, then 1x1 conv3 ----
    float r8[8];
#pragma unroll
    for (int p = 0; p < 4; p++) {
        float lo0, hi0, lo1, hi1, lo2, hi2, lo3, hi3;
        upk2(acc[0][p], lo0, hi0);
        upk2(acc[1][p], lo1, hi1);
        upk2(acc[2][p], lo2, hi2);
        upk2(acc[3][p], lo3, hi3);
        float mlo = fmaxf(fmaxf(lo0, lo1), fmaxf(lo2, lo3));
        float mhi = fmaxf(fmaxf(hi0, hi1), fmaxf(hi2, hi3));
        r8[2 * p]     = fmaxf(mlo + b2s[2 * p], 0.f);
        r8[2 * p + 1] = fmaxf(mhi + b2s[2 * p + 1], 0.f);
    }

    const int oy = py0 + ty, ox = px0 + tx;
    const int pix = oy * 64 + ox;
#pragma unroll
    for (int oc = 0; oc < 4; oc++) {
        float s = b3s[oc];
#pragma unroll
        for (int ic = 0; ic < 8; ic++) s = fmaf(w3s[oc * 8 + ic], r8[ic], s);
        low[((size_t)img * 4 + oc) * 4096 + pix] = s;
    }
}

// ---------------------------------------------------------------------------
extern "C" void kernel_launch(void* const* d_in, const int* in_sizes, int n_in,
                              void* d_out, int out_size) {
    const float* x  = (const float*)d_in[0];
    const float* w1 = (const float*)d_in[1];
    const float* b1 = (const float*)d_in[2];
    const float* w2 = (const float*)d_in[3];
    const float* b2 = (const float*)d_in[4];
    const float* w3 = (const float*)d_in[5];
    const float* b3 = (const float*)d_in[6];

    float* out  = (float*)d_out;
    float* low  = out;                    // 96*4*64*64 = 1,572,864 floats
    float* high = out + 1572864;          // 96*2*256*256 = 12,582,912 floats

    dwt_kernel<<<dim3(256, 96), 128>>>(x, high);
    fused_kernel<<<dim3(4, 4, NIMG), dim3(16, 16)>>>(w1, b1, w2, b2, w3, b3, low);
}